// round 2
// baseline (speedup 1.0000x reference)
#include <cuda_runtime.h>

#define B_   8
#define C_   256
#define HW   4096
#define OC3  768
#define GRPS 96

// Scratch (alloc-free rule: __device__ globals)
__device__ float g_qkv[B_ * OC3 * HW];   // ~100.7 MB
__device__ float g_agg[B_ * OC3 * HW];   // ~100.7 MB
__device__ float g_kv [B_ * 64 * 72];    // per (b,head) 8x9 kv matrix

// ---------------------------------------------------------------------------
// K1: qkv[b,o,n] = sum_c w_qkv[o,c] * x[b,c,n]   (per-batch 768x256 @ 256x4096)
// 128x128 tile, BK=8, 256 threads, 8x8 microtile
// ---------------------------------------------------------------------------
__global__ __launch_bounds__(256) void qkv_gemm_k(const float* __restrict__ x,
                                                  const float* __restrict__ w)
{
    int b = blockIdx.z;
    const float* xb = x + (size_t)b * C_ * HW;
    float* ob = g_qkv + (size_t)b * OC3 * HW;
    int n0 = blockIdx.x * 128, m0 = blockIdx.y * 128;

    __shared__ float As[8][128];
    __shared__ float Bs[8][128];
    float acc[8][8] = {};
    int tid = threadIdx.x;
    int tm = (tid >> 4) << 3, tn = (tid & 15) << 3;

    for (int k0 = 0; k0 < C_; k0 += 8) {
        {
            int arow = tid >> 1, ak = (tid & 1) << 2;
            float4 a4 = *(const float4*)(w + (size_t)(m0 + arow) * C_ + k0 + ak);
            As[ak + 0][arow] = a4.x; As[ak + 1][arow] = a4.y;
            As[ak + 2][arow] = a4.z; As[ak + 3][arow] = a4.w;
        }
        {
            int brow = tid >> 5, bn = (tid & 31) << 2;
            *(float4*)&Bs[brow][bn] =
                *(const float4*)(xb + (size_t)(k0 + brow) * HW + n0 + bn);
        }
        __syncthreads();
        #pragma unroll
        for (int kk = 0; kk < 8; kk++) {
            float a[8], bb[8];
            *(float4*)(a)      = *(float4*)&As[kk][tm];
            *(float4*)(a + 4)  = *(float4*)&As[kk][tm + 4];
            *(float4*)(bb)     = *(float4*)&Bs[kk][tn];
            *(float4*)(bb + 4) = *(float4*)&Bs[kk][tn + 4];
            #pragma unroll
            for (int i = 0; i < 8; i++)
                #pragma unroll
                for (int j = 0; j < 8; j++)
                    acc[i][j] = fmaf(a[i], bb[j], acc[i][j]);
        }
        __syncthreads();
    }
    #pragma unroll
    for (int i = 0; i < 8; i++) {
        float4* d0 = (float4*)(ob + (size_t)(m0 + tm + i) * HW + n0 + tn);
        d0[0] = make_float4(acc[i][0], acc[i][1], acc[i][2], acc[i][3]);
        d0[1] = make_float4(acc[i][4], acc[i][5], acc[i][6], acc[i][7]);
    }
}

// ---------------------------------------------------------------------------
// K2: fused depthwise 5x5 (pad 2, cross-correlation) + grouped 8x8 pointwise.
// One block = (b, group g, 32x32 spatial tile). Reads qkv, writes agg.
// ---------------------------------------------------------------------------
__global__ __launch_bounds__(256) void dw_agg_k(const float* __restrict__ wdw,
                                                const float* __restrict__ wpw)
{
    int bg = blockIdx.z;
    int b = bg / GRPS, g = bg % GRPS;
    int y0 = blockIdx.y * 32, x0 = blockIdx.x * 32;

    __shared__ float s[8][36][36];
    __shared__ float swd[8][25];
    __shared__ float swp[64];
    int tid = threadIdx.x;

    if (tid < 200) swd[tid / 25][tid % 25] = wdw[(size_t)(g * 8 + tid / 25) * 25 + tid % 25];
    if (tid < 64)  swp[tid] = wpw[(size_t)g * 64 + tid];

    const float* src = g_qkv + ((size_t)b * OC3 + g * 8) * HW;
    for (int i = tid; i < 8 * 36 * 36; i += 256) {
        int ch = i / 1296, r = (i % 1296) / 36, c = i % 36;
        int y = y0 + r - 2, x = x0 + c - 2;
        float v = 0.f;
        if ((unsigned)y < 64u && (unsigned)x < 64u) v = src[(size_t)ch * HW + y * 64 + x];
        s[ch][r][c] = v;
    }
    __syncthreads();

    float* dst = g_agg + ((size_t)b * OC3 + g * 8) * HW;
    for (int p = tid; p < 1024; p += 256) {
        int py = p >> 5, px = p & 31;
        float dwv[8];
        #pragma unroll
        for (int ch = 0; ch < 8; ch++) {
            float a = 0.f;
            #pragma unroll
            for (int dy = 0; dy < 5; dy++)
                #pragma unroll
                for (int dx = 0; dx < 5; dx++)
                    a = fmaf(s[ch][py + dy][px + dx], swd[ch][dy * 5 + dx], a);
            dwv[ch] = a;
        }
        int off = (y0 + py) * 64 + x0 + px;
        #pragma unroll
        for (int o = 0; o < 8; o++) {
            float a = 0.f;
            #pragma unroll
            for (int i2 = 0; i2 < 8; i2++) a = fmaf(swp[o * 8 + i2], dwv[i2], a);
            dst[(size_t)o * HW + off] = a;
        }
    }
}

// ---------------------------------------------------------------------------
// K3: kv[b,h][d][e] = sum_n relu(k[n,d]) * v_pad[n,e]  (e=8 -> ones column).
// head h<32 -> qkv buffer, h>=32 -> agg buffer; channels 24*hh + {8..15 k, 16..23 v}.
// Deterministic: shuffle reduce within warp, smem tree across 8 warps.
// ---------------------------------------------------------------------------
__global__ __launch_bounds__(256) void kv_k()
{
    int bh = blockIdx.x;
    int b = bh >> 6, h = bh & 63;
    const float* base = (h < 32 ? g_qkv : g_agg) + ((size_t)b * OC3 + (h & 31) * 24) * HW;
    const float* kp = base + 8 * HW;
    const float* vp = base + 16 * HW;

    float acc[8][9] = {};
    for (int n = threadIdx.x; n < HW; n += 256) {
        float kr[8], vr[8];
        #pragma unroll
        for (int d = 0; d < 8; d++) {
            kr[d] = fmaxf(kp[(size_t)d * HW + n], 0.f);
            vr[d] = vp[(size_t)d * HW + n];
        }
        #pragma unroll
        for (int d = 0; d < 8; d++) {
            #pragma unroll
            for (int e = 0; e < 8; e++) acc[d][e] = fmaf(kr[d], vr[e], acc[d][e]);
            acc[d][8] += kr[d];
        }
    }
    __shared__ float sred[8][72];
    int w = threadIdx.x >> 5, lane = threadIdx.x & 31;
    #pragma unroll
    for (int d = 0; d < 8; d++)
        #pragma unroll
        for (int e = 0; e < 9; e++) {
            float v = acc[d][e];
            #pragma unroll
            for (int o = 16; o > 0; o >>= 1) v += __shfl_down_sync(0xffffffffu, v, o);
            if (lane == 0) sred[w][d * 9 + e] = v;
        }
    __syncthreads();
    if (threadIdx.x < 72) {
        float v = 0.f;
        #pragma unroll
        for (int w2 = 0; w2 < 8; w2++) v += sred[w2][threadIdx.x];
        g_kv[(size_t)bh * 72 + threadIdx.x] = v;
    }
}

// ---------------------------------------------------------------------------
// K4: fused attention + proj GEMM + BN + residual.
// out[b,o,n] = x[b,o,n] + BN( sum_c wproj[o,c] * att[b,c,n] )
// att channel c = head*8+e, generated on-the-fly into smem per 8-head chunk.
// Block: 128 outputs x 128 tokens; K=512 in 8 chunks of 64.
// Dynamic smem 84KB: kv (4608) + As[64][128] + att_s[64][128].
// ---------------------------------------------------------------------------
__global__ __launch_bounds__(256) void att_proj_k(const float* __restrict__ wproj,
    const float* __restrict__ x, const float* __restrict__ gamma,
    const float* __restrict__ beta, const float* __restrict__ mean,
    const float* __restrict__ var, float* __restrict__ out)
{
    extern __shared__ float sm[];
    float* kv_s  = sm;                    // 64*72
    float* As    = sm + 4608;             // [k][m] 64*128
    float* att_s = sm + 4608 + 8192;      // [k][n] 64*128

    int b = blockIdx.z;
    int n0 = blockIdx.x * 128;
    int m0 = blockIdx.y * 128;
    int tid = threadIdx.x;

    for (int i = tid; i < 4608; i += 256) kv_s[i] = g_kv[(size_t)b * 4608 + i];
    __syncthreads();

    float acc[8][8] = {};
    int tm = (tid >> 4) << 3, tn = (tid & 15) << 3;
    int nl = tid & 127, hb = tid >> 7;

    for (int hc = 0; hc < 8; hc++) {
        // stage W chunk transposed into As[k][m]; row=tid&127 across warp
        // -> conflict-free smem stores, L1 absorbs the strided global reads
        #pragma unroll
        for (int i = 0; i < 8; i++) {
            int idx = i * 256 + tid;
            int row = idx & 127, kq = (idx >> 7) << 2;
            float4 wv = *(const float4*)(wproj + (size_t)(m0 + row) * 512 + hc * 64 + kq);
            As[(kq + 0) * 128 + row] = wv.x;
            As[(kq + 1) * 128 + row] = wv.y;
            As[(kq + 2) * 128 + row] = wv.z;
            As[(kq + 3) * 128 + row] = wv.w;
        }
        // generate att chunk: 8 heads x 128 tokens
        #pragma unroll
        for (int i = 0; i < 4; i++) {
            int hl = hb + i * 2;
            int h = hc * 8 + hl;
            const float* src = (h < 32 ? g_qkv : g_agg)
                             + ((size_t)b * OC3 + (h & 31) * 24) * HW + n0 + nl;
            float q[8];
            #pragma unroll
            for (int d = 0; d < 8; d++) q[d] = fmaxf(src[(size_t)d * HW], 0.f);
            const float* kvh = kv_s + h * 72;
            float den = 0.f;
            #pragma unroll
            for (int d = 0; d < 8; d++) den = fmaf(q[d], kvh[d * 9 + 8], den);
            float inv = 1.f / (den + 1e-15f);
            #pragma unroll
            for (int e = 0; e < 8; e++) {
                float s = 0.f;
                #pragma unroll
                for (int d = 0; d < 8; d++) s = fmaf(q[d], kvh[d * 9 + e], s);
                att_s[(hl * 8 + e) * 128 + nl] = s * inv;
            }
        }
        __syncthreads();
        #pragma unroll 8
        for (int kk = 0; kk < 64; kk++) {
            float a[8], bb[8];
            *(float4*)(a)      = *(float4*)&As[kk * 128 + tm];
            *(float4*)(a + 4)  = *(float4*)&As[kk * 128 + tm + 4];
            *(float4*)(bb)     = *(float4*)&att_s[kk * 128 + tn];
            *(float4*)(bb + 4) = *(float4*)&att_s[kk * 128 + tn + 4];
            #pragma unroll
            for (int i = 0; i < 8; i++)
                #pragma unroll
                for (int j = 0; j < 8; j++)
                    acc[i][j] = fmaf(a[i], bb[j], acc[i][j]);
        }
        __syncthreads();
    }
    #pragma unroll
    for (int i = 0; i < 8; i++) {
        int o = m0 + tm + i;
        float invg = gamma[o] / sqrtf(var[o] + 1e-6f);
        float bias = beta[o] - mean[o] * invg;
        size_t off = ((size_t)b * C_ + o) * HW + n0 + tn;
        float4 x0 = *(const float4*)(x + off);
        float4 x1 = *(const float4*)(x + off + 4);
        float4 r0, r1;
        r0.x = x0.x + acc[i][0] * invg + bias;
        r0.y = x0.y + acc[i][1] * invg + bias;
        r0.z = x0.z + acc[i][2] * invg + bias;
        r0.w = x0.w + acc[i][3] * invg + bias;
        r1.x = x1.x + acc[i][4] * invg + bias;
        r1.y = x1.y + acc[i][5] * invg + bias;
        r1.z = x1.z + acc[i][6] * invg + bias;
        r1.w = x1.w + acc[i][7] * invg + bias;
        *(float4*)(out + off)     = r0;
        *(float4*)(out + off + 4) = r1;
    }
}

// ---------------------------------------------------------------------------
extern "C" void kernel_launch(void* const* d_in, const int* in_sizes, int n_in,
                              void* d_out, int out_size)
{
    const float* x     = (const float*)d_in[0];
    const float* wqkv  = (const float*)d_in[1];
    const float* wdw   = (const float*)d_in[2];
    const float* wpw   = (const float*)d_in[3];
    const float* wproj = (const float*)d_in[4];
    const float* gamma = (const float*)d_in[5];
    const float* beta  = (const float*)d_in[6];
    const float* mean  = (const float*)d_in[7];
    const float* var   = (const float*)d_in[8];
    float* out = (float*)d_out;

    qkv_gemm_k<<<dim3(32, 6, 8), 256>>>(x, wqkv);
    dw_agg_k<<<dim3(2, 2, B_ * GRPS), 256>>>(wdw, wpw);
    kv_k<<<B_ * 64, 256>>>();

    const int smem = (4608 + 8192 + 8192) * (int)sizeof(float);  // 83968
    cudaFuncSetAttribute(att_proj_k, cudaFuncAttributeMaxDynamicSharedMemorySize, smem);
    att_proj_k<<<dim3(32, 2, B_), 256, smem>>>(wproj, x, gamma, beta, mean, var, out);
}